// round 1
// baseline (speedup 1.0000x reference)
#include <cuda_runtime.h>

#define N_USERS   100000
#define N_ITEMS   50000
#define NTOT      (N_USERS + N_ITEMS)   // 150000
#define D         64
#define NNZV      2000000
#define BATCHN    4096
#define N_LAYERS  3

// Scratch (device globals; allocation-free rule). Reused across both graphs.
__device__ float g_bufA[NTOT * D];
__device__ float g_bufB[NTOT * D];
__device__ float g_sum [NTOT * D];
__device__ int   g_rowptr[NTOT + 1];

// cur = sum = concat(user_emb, item_emb)
__global__ void init_kernel(const float* __restrict__ ue,
                            const float* __restrict__ ie,
                            float* __restrict__ cur,
                            float* __restrict__ sum) {
    int i = blockIdx.x * blockDim.x + threadIdx.x;
    if (i >= NTOT * D) return;
    float v = (i < N_USERS * D) ? ue[i] : ie[i - N_USERS * D];
    cur[i] = v;
    sum[i] = v;
}

// rows is sorted -> build CSR row_ptr. Gaps are tiny (rows ~uniform, 13.3 nnz/row).
__global__ void rowptr_kernel(const int* __restrict__ rows, int* __restrict__ rowptr) {
    int k = blockIdx.x * blockDim.x + threadIdx.x;
    if (k >= NNZV) return;
    int r  = rows[k];
    int rp = (k == 0) ? -1 : rows[k - 1];
    for (int j = rp + 1; j <= r; ++j) rowptr[j] = k;
    if (k == NNZV - 1) {
        for (int j = r + 1; j <= NTOT; ++j) rowptr[j] = NNZV;
    }
}

// One warp per output row. Each lane owns a float2 (64 floats / 32 lanes).
// nxt[r] = sum_k vals[k]*cur[cols[k]];  sum[r] += nxt[r]  (fused epilogue).
__global__ void __launch_bounds__(256)
spmm_kernel(const int*   __restrict__ rowptr,
            const int*   __restrict__ cols,
            const float* __restrict__ vals,
            const float* __restrict__ cur,
            float*       __restrict__ nxt,
            float*       __restrict__ sum) {
    int warp = (blockIdx.x * blockDim.x + threadIdx.x) >> 5;
    int lane = threadIdx.x & 31;
    if (warp >= NTOT) return;

    int start = rowptr[warp];
    int end   = rowptr[warp + 1];

    const float2* __restrict__ c2 = (const float2*)cur;
    float ax = 0.f, ay = 0.f;

    int k = start;
    // unroll x4 for MLP: 4 independent 256B gathers in flight per warp
    for (; k + 3 < end; k += 4) {
        int   i0 = cols[k],     i1 = cols[k + 1];
        int   i2 = cols[k + 2], i3 = cols[k + 3];
        float v0 = vals[k],     v1 = vals[k + 1];
        float v2 = vals[k + 2], v3 = vals[k + 3];
        float2 e0 = c2[i0 * 32 + lane];
        float2 e1 = c2[i1 * 32 + lane];
        float2 e2 = c2[i2 * 32 + lane];
        float2 e3 = c2[i3 * 32 + lane];
        ax += v0 * e0.x; ay += v0 * e0.y;
        ax += v1 * e1.x; ay += v1 * e1.y;
        ax += v2 * e2.x; ay += v2 * e2.y;
        ax += v3 * e3.x; ay += v3 * e3.y;
    }
    for (; k < end; ++k) {
        int   c = cols[k];
        float v = vals[k];
        float2 e = c2[c * 32 + lane];
        ax += v * e.x; ay += v * e.y;
    }

    int o = warp * 32 + lane;
    ((float2*)nxt)[o] = make_float2(ax, ay);
    float2 s = ((float2*)sum)[o];
    ((float2*)sum)[o] = make_float2(s.x + ax, s.y + ay);
}

// Gather 3 slices for one graph: users / pos_items / neg_items.
// light = sum * 0.25 folded in here. One warp per (slice, batch) pair.
__global__ void gather_kernel(const float* __restrict__ sum,
                              const int* __restrict__ users,
                              const int* __restrict__ pos,
                              const int* __restrict__ neg,
                              float* __restrict__ out) {
    int warp = (blockIdx.x * blockDim.x + threadIdx.x) >> 5;
    int lane = threadIdx.x & 31;
    if (warp >= 3 * BATCHN) return;
    int s = warp / BATCHN;
    int b = warp - s * BATCHN;
    int idx;
    if (s == 0)      idx = users[b];
    else if (s == 1) idx = N_USERS + pos[b];
    else             idx = N_USERS + neg[b];
    float2 e = ((const float2*)sum)[idx * 32 + lane];
    ((float2*)out)[(s * BATCHN + b) * 32 + lane] =
        make_float2(e.x * 0.25f, e.y * 0.25f);
}

extern "C" void kernel_launch(void* const* d_in, const int* in_sizes, int n_in,
                              void* d_out, int out_size) {
    (void)in_sizes; (void)n_in; (void)out_size;

    float* bufA; float* bufB; float* sum; int* rowptr;
    cudaGetSymbolAddress((void**)&bufA,   g_bufA);
    cudaGetSymbolAddress((void**)&bufB,   g_bufB);
    cudaGetSymbolAddress((void**)&sum,    g_sum);
    cudaGetSymbolAddress((void**)&rowptr, g_rowptr);

    float* out = (float*)d_out;

    const int initGrid   = (NTOT * D + 255) / 256;
    const int rpGrid     = (NNZV + 255) / 256;
    const int spmmGrid   = (NTOT + 7) / 8;          // 8 warps/block, 1 warp/row
    const int gatherGrid = (3 * BATCHN + 7) / 8;

    for (int g = 0; g < 2; ++g) {
        const int*   rows = (const int*)  d_in[g * 3 + 0];
        const int*   cols = (const int*)  d_in[g * 3 + 1];
        const float* vals = (const float*)d_in[g * 3 + 2];
        const float* ue   = (const float*)d_in[6 + g * 2 + 0];
        const float* ie   = (const float*)d_in[6 + g * 2 + 1];
        const int*   bu   = (const int*)  d_in[10 + g * 3 + 0];
        const int*   bp   = (const int*)  d_in[10 + g * 3 + 1];
        const int*   bn   = (const int*)  d_in[10 + g * 3 + 2];

        init_kernel<<<initGrid, 256>>>(ue, ie, bufA, sum);
        rowptr_kernel<<<rpGrid, 256>>>(rows, rowptr);

        float* cur = bufA;
        float* nxt = bufB;
        for (int layer = 0; layer < N_LAYERS; ++layer) {
            spmm_kernel<<<spmmGrid, 256>>>(rowptr, cols, vals, cur, nxt, sum);
            float* t = cur; cur = nxt; nxt = t;
        }

        gather_kernel<<<gatherGrid, 256>>>(sum, bu, bp, bn,
                                           out + (size_t)g * 3 * BATCHN * D);
    }
}

// round 2
// speedup vs baseline: 1.5986x; 1.5986x over previous
#include <cuda_runtime.h>

#define N_USERS   100000
#define N_ITEMS   50000
#define NTOT      (N_USERS + N_ITEMS)   // 150000
#define D         64
#define NNZV      2000000
#define BATCHN    4096
#define N_LAYERS  3

// Per-graph, per-layer embedding buffers (e0..e3). 2*4*38.4MB = 307MB.
__device__ float g_e[2][4][NTOT * D];
__device__ int   g_rowptr[2][NTOT + 1];

// rows is sorted -> build CSR row_ptr (rows ~uniform, 13.3 nnz/row).
__global__ void rowptr_kernel(const int* __restrict__ rows, int* __restrict__ rowptr) {
    int k = blockIdx.x * blockDim.x + threadIdx.x;
    if (k >= NNZV) return;
    int r  = rows[k];
    int rp = (k == 0) ? -1 : rows[k - 1];
    for (int j = rp + 1; j <= r; ++j) rowptr[j] = k;
    if (k == NNZV - 1) {
        for (int j = r + 1; j <= NTOT; ++j) rowptr[j] = NNZV;
    }
}

// SpMM: one HALF-warp (16 lanes) per output row, float4 per lane (64 floats).
// Two independent rows per warp -> 2x row-level MLP, half the LDG count vs float2.
__global__ void __launch_bounds__(256)
spmm_kernel(const int*    __restrict__ rowptr,
            const int*    __restrict__ cols,
            const float*  __restrict__ vals,
            const float4* __restrict__ cur,
            float4*       __restrict__ nxt) {
    int warp = (blockIdx.x * blockDim.x + threadIdx.x) >> 5;
    int lane = threadIdx.x & 31;
    int half = lane >> 4;
    int l16  = lane & 15;
    int row  = warp * 2 + half;
    if (row >= NTOT) return;

    int start = rowptr[row];
    int end   = rowptr[row + 1];

    float4 acc = make_float4(0.f, 0.f, 0.f, 0.f);

    int k = start;
    // unroll x4: 4 independent 256B row-gathers in flight per half-warp
    for (; k + 3 < end; k += 4) {
        int   i0 = cols[k],     i1 = cols[k + 1];
        int   i2 = cols[k + 2], i3 = cols[k + 3];
        float v0 = vals[k],     v1 = vals[k + 1];
        float v2 = vals[k + 2], v3 = vals[k + 3];
        float4 e0 = cur[i0 * 16 + l16];
        float4 e1 = cur[i1 * 16 + l16];
        float4 e2 = cur[i2 * 16 + l16];
        float4 e3 = cur[i3 * 16 + l16];
        acc.x += v0 * e0.x; acc.y += v0 * e0.y; acc.z += v0 * e0.z; acc.w += v0 * e0.w;
        acc.x += v1 * e1.x; acc.y += v1 * e1.y; acc.z += v1 * e1.z; acc.w += v1 * e1.w;
        acc.x += v2 * e2.x; acc.y += v2 * e2.y; acc.z += v2 * e2.z; acc.w += v2 * e2.w;
        acc.x += v3 * e3.x; acc.y += v3 * e3.y; acc.z += v3 * e3.z; acc.w += v3 * e3.w;
    }
    for (; k < end; ++k) {
        int   c = cols[k];
        float v = vals[k];
        float4 e = cur[c * 16 + l16];
        acc.x += v * e.x; acc.y += v * e.y; acc.z += v * e.z; acc.w += v * e.w;
    }

    nxt[row * 16 + l16] = acc;
}

// Gather + mean over the 4 layer buffers, only at the 3*4096 needed rows.
// One 16-lane group per (slice, batch) pair; float4 per lane.
__global__ void gather_kernel(const float4* __restrict__ e0,
                              const float4* __restrict__ e1,
                              const float4* __restrict__ e2,
                              const float4* __restrict__ e3,
                              const int* __restrict__ users,
                              const int* __restrict__ pos,
                              const int* __restrict__ neg,
                              float4* __restrict__ out) {
    int t   = blockIdx.x * blockDim.x + threadIdx.x;
    int r   = t >> 4;
    int l16 = t & 15;
    if (r >= 3 * BATCHN) return;
    int s = r / BATCHN;
    int b = r - s * BATCHN;
    int idx;
    if (s == 0)      idx = users[b];
    else if (s == 1) idx = N_USERS + pos[b];
    else             idx = N_USERS + neg[b];

    int o = idx * 16 + l16;
    float4 a = e0[o], bb = e1[o], c = e2[o], d = e3[o];
    float4 m;
    m.x = (a.x + bb.x + c.x + d.x) * 0.25f;
    m.y = (a.y + bb.y + c.y + d.y) * 0.25f;
    m.z = (a.z + bb.z + c.z + d.z) * 0.25f;
    m.w = (a.w + bb.w + c.w + d.w) * 0.25f;
    out[r * 16 + l16] = m;
}

extern "C" void kernel_launch(void* const* d_in, const int* in_sizes, int n_in,
                              void* d_out, int out_size) {
    (void)in_sizes; (void)n_in; (void)out_size;

    // One-time infra (host-side handles only; no device allocations).
    static cudaStream_t s2 = nullptr;
    static cudaEvent_t  evFork = nullptr, evJoin = nullptr;
    if (!s2) {
        cudaStreamCreate(&s2);
        cudaEventCreateWithFlags(&evFork, cudaEventDisableTiming);
        cudaEventCreateWithFlags(&evJoin, cudaEventDisableTiming);
    }

    float* eBase;  int* rpBase;
    cudaGetSymbolAddress((void**)&eBase,  g_e);
    cudaGetSymbolAddress((void**)&rpBase, g_rowptr);

    float* out = (float*)d_out;

    const int rpGrid     = (NNZV + 255) / 256;
    const int spmmGrid   = (NTOT / 2 + 7) / 8;           // 2 rows/warp, 8 warps/block
    const int gatherGrid = (3 * BATCHN * 16 + 255) / 256;

    // Fork: graph 1 runs on s2, graph 0 on the capture (default) stream.
    cudaEventRecord(evFork, 0);
    cudaStreamWaitEvent(s2, evFork, 0);

    for (int g = 0; g < 2; ++g) {
        cudaStream_t st = g ? s2 : 0;

        const int*   rows = (const int*)  d_in[g * 3 + 0];
        const int*   cols = (const int*)  d_in[g * 3 + 1];
        const float* vals = (const float*)d_in[g * 3 + 2];
        const float* ue   = (const float*)d_in[6 + g * 2 + 0];
        const float* ie   = (const float*)d_in[6 + g * 2 + 1];
        const int*   bu   = (const int*)  d_in[10 + g * 3 + 0];
        const int*   bp   = (const int*)  d_in[10 + g * 3 + 1];
        const int*   bn   = (const int*)  d_in[10 + g * 3 + 2];

        float* e[4];
        for (int l = 0; l < 4; ++l) e[l] = eBase + ((size_t)g * 4 + l) * (NTOT * D);
        int* rowptr = rpBase + g * (NTOT + 1);

        // e0 = concat(user_emb, item_emb)  (D2D async copies; capture-legal)
        cudaMemcpyAsync(e[0], ue, (size_t)N_USERS * D * sizeof(float),
                        cudaMemcpyDeviceToDevice, st);
        cudaMemcpyAsync(e[0] + (size_t)N_USERS * D, ie,
                        (size_t)N_ITEMS * D * sizeof(float),
                        cudaMemcpyDeviceToDevice, st);

        rowptr_kernel<<<rpGrid, 256, 0, st>>>(rows, rowptr);

        for (int layer = 0; layer < N_LAYERS; ++layer) {
            spmm_kernel<<<spmmGrid, 256, 0, st>>>(
                rowptr, cols, vals,
                (const float4*)e[layer], (float4*)e[layer + 1]);
        }

        gather_kernel<<<gatherGrid, 256, 0, st>>>(
            (const float4*)e[0], (const float4*)e[1],
            (const float4*)e[2], (const float4*)e[3],
            bu, bp, bn,
            (float4*)(out + (size_t)g * 3 * BATCHN * D));
    }

    // Join: capture stream waits for s2's chain.
    cudaEventRecord(evJoin, s2);
    cudaStreamWaitEvent(0, evJoin, 0);
}